// round 16
// baseline (speedup 1.0000x reference)
#include <cuda_runtime.h>
#include <math.h>

// Problem constants (fixed shapes from reference setup_inputs)
#define B_      4
#define C_      256
#define P_      65536          // H*W = 256*256
#define NSEG    32             // object ids 1..32
#define PT      1024           // pixels per tile
#define TILES_PER_B (P_ / PT)  // 64
#define CH      128            // channels per block (tile split in 2)
#define NQH     (CH / 4)       // 32 channel-quads per block
#define NBLK1   (B_ * TILES_PER_B * 2)  // 512 pooling blocks (+1 wf block)
#define THREADS1 256

// Global segmented maxima as non-negative float bit-patterns: [b][seg][c], 128 KB.
// INVARIANT: zero at kernel_launch entry (zero-initialized at module load;
// mlp_kernel re-zeros after consuming, so every call/replay sees zeros).
__device__ int g_gmax[B_ * NSEG * C_];
// Fused MLP weight Wf = w1@w2 [256][4] and bias = b2 + b1@w2 [4]
__device__ float g_wf[C_ * 4];
__device__ float g_bias[4];

// ---------------------------------------------------------------------------
// Phase 1: per-(tile, channel-half) segmented max. accum [cquad][id][4ch];
// one LDS.128 snapshots 4 channels' maxima for a pixel's id. Non-negative
// float bits (init 0 == clamp at 0; int cmp == float cmp); stale snapshots
// safe (monotone). 4+4 double-buffered loads; 512 blocks -> ~3.5 CTAs/SM.
// Flush: fire-and-forget REDG.MAX to g_gmax — NO fence (R14 measured +20us).
// PDL: every block signals launch_dependents at entry so the mlp kernel's
// blocks get scheduled during the pooling wave; its griddepcontrol.wait
// releases only after this whole grid completes + memory is flushed.
// The LAST block computes Wf = w1@w2 and bias = b2 + b1@w2 instead.
// ---------------------------------------------------------------------------
__global__ __launch_bounds__(THREADS1, 4)
void seg_pool_kernel(const float* __restrict__ enc, const int* __restrict__ masks,
                     const float* __restrict__ w1, const float* __restrict__ b1,
                     const float* __restrict__ w2, const float* __restrict__ b2) {
    asm volatile("griddepcontrol.launch_dependents;");   // PDL: let mlp schedule now

    const int blk  = blockIdx.x;
    const int tid  = threadIdx.x;
    const int warp = tid >> 5;
    const int lane = tid & 31;

    if (blk == NBLK1) {
        // ---- fused-weight block: 8 warps cover 256 c-rows, 32 rows each ----
        for (int r = 0; r < 32; r++) {
            const int c = r * 8 + warp;
            float a0 = 0.f, a1 = 0.f, a2 = 0.f, a3 = 0.f;
            #pragma unroll
            for (int k = 0; k < 4; k++) {
                const int j = lane + 32 * k;
                const float a = w1[c * 128 + j];
                const float4 wr = *reinterpret_cast<const float4*>(w2 + j * 4);
                a0 = fmaf(a, wr.x, a0); a1 = fmaf(a, wr.y, a1);
                a2 = fmaf(a, wr.z, a2); a3 = fmaf(a, wr.w, a3);
            }
            #pragma unroll
            for (int d = 16; d >= 1; d >>= 1) {
                a0 += __shfl_xor_sync(0xffffffffu, a0, d);
                a1 += __shfl_xor_sync(0xffffffffu, a1, d);
                a2 += __shfl_xor_sync(0xffffffffu, a2, d);
                a3 += __shfl_xor_sync(0xffffffffu, a3, d);
            }
            if (lane == 0)
                *reinterpret_cast<float4*>(g_wf + c * 4) = make_float4(a0, a1, a2, a3);
        }
        if (warp == 0) {
            float s0 = 0.f, s1 = 0.f, s2 = 0.f, s3 = 0.f;
            #pragma unroll
            for (int k = 0; k < 4; k++) {
                const int j = lane + 32 * k;
                const float bv = b1[j];
                const float4 wr = *reinterpret_cast<const float4*>(w2 + j * 4);
                s0 = fmaf(bv, wr.x, s0); s1 = fmaf(bv, wr.y, s1);
                s2 = fmaf(bv, wr.z, s2); s3 = fmaf(bv, wr.w, s3);
            }
            #pragma unroll
            for (int d = 16; d >= 1; d >>= 1) {
                s0 += __shfl_xor_sync(0xffffffffu, s0, d);
                s1 += __shfl_xor_sync(0xffffffffu, s1, d);
                s2 += __shfl_xor_sync(0xffffffffu, s2, d);
                s3 += __shfl_xor_sync(0xffffffffu, s3, d);
            }
            if (lane == 0) {
                g_bias[0] = s0 + b2[0];
                g_bias[1] = s1 + b2[1];
                g_bias[2] = s2 + b2[2];
                g_bias[3] = s3 + b2[3];
            }
        }
        return;
    }

    __shared__ int4 accum4[NQH * 33];           // 16.9 KB
    int* accum = reinterpret_cast<int*>(accum4);

    // block -> (batch, tile, channel-half)
    const int b    = blk / (TILES_PER_B * 2);
    const int rem  = blk % (TILES_PER_B * 2);
    const int tile = rem >> 1;
    const int half = rem & 1;                   // 0: ch 0..127, 1: 128..255
    const int choff = half * CH;

    #pragma unroll
    for (int i = tid; i < NQH * 33 * 4; i += THREADS1) accum[i] = 0;

    const int pbase = tile * PT;
    const int4 idv = reinterpret_cast<const int4*>(masks + (size_t)b * P_ + pbase)[tid];
    const int id0 = idv.x, id1 = idv.y, id2 = idv.z, id3 = idv.w;

    __syncthreads();

    const float* encb = enc + ((size_t)b * C_ + choff) * P_ + pbase;

    #define LOADV(DST, CBASE)                                                   \
        _Pragma("unroll")                                                       \
        for (int u = 0; u < 4; u++)                                             \
            DST[u] = reinterpret_cast<const float4*>(encb + (size_t)((CBASE) + u) * P_)[tid];

    // one channel-quad (4 consecutive channels), 4 pixels per thread
    #define CHECK_PIXEL(CQ, IDX, SRC, COMP)                                     \
    {                                                                           \
        const int4 cur = accum4[(CQ) * 33 + IDX];                               \
        const int base = ((CQ) * 33 + IDX) * 4; int a;                          \
        a = __float_as_int(SRC[0].COMP); if (a > cur.x) atomicMax(&accum[base+0], a); \
        a = __float_as_int(SRC[1].COMP); if (a > cur.y) atomicMax(&accum[base+1], a); \
        a = __float_as_int(SRC[2].COMP); if (a > cur.z) atomicMax(&accum[base+2], a); \
        a = __float_as_int(SRC[3].COMP); if (a > cur.w) atomicMax(&accum[base+3], a); \
    }

    #define PROCESS(SRC, CBASE)                                                 \
    {                                                                           \
        const int cq = (CBASE) >> 2;                                            \
        CHECK_PIXEL(cq, id0, SRC, x)                                            \
        CHECK_PIXEL(cq, id1, SRC, y)                                            \
        CHECK_PIXEL(cq, id2, SRC, z)                                            \
        CHECK_PIXEL(cq, id3, SRC, w)                                            \
    }

    float4 va[4], vb[4];
    LOADV(va, 0)
    #pragma unroll 1
    for (int c0 = 0; c0 < CH; c0 += 8) {
        LOADV(vb, c0 + 4)
        PROCESS(va, c0)
        if (c0 + 8 < CH) { LOADV(va, c0 + 8) }
        PROCESS(vb, c0 + 4)
    }
    #undef LOADV
    #undef PROCESS
    #undef CHECK_PIXEL

    __syncthreads();

    // flush this half's channels straight to global maxima (drop id 0);
    // fire-and-forget REDG.MAX — no round trip, no fence.
    #pragma unroll
    for (int i = tid; i < NSEG * CH; i += THREADS1) {
        const int s  = i >> 7;       // 0..31
        const int cl = i & 127;      // local channel 0..127
        atomicMax(&g_gmax[(b * NSEG + s) * C_ + choff + cl],
                  accum[((cl >> 2) * 33 + s + 1) * 4 + (cl & 3)]);
    }
}

// ---------------------------------------------------------------------------
// Phase 2 (PDL secondary): blocks are scheduled during the pooling wave and
// sleep in griddepcontrol.wait; it releases after seg_pool fully completes
// (memory flushed), so all REDG results are visible. Then: multiply by fused
// weight, 4-warp tree sum, sigmoid; re-zero own g_gmax slice (replay invariant).
// ---------------------------------------------------------------------------
__global__ __launch_bounds__(1024)
void mlp_kernel(float* __restrict__ out) {
    __shared__ float mlp[4][C_];     // 4 KB

    asm volatile("griddepcontrol.wait;" ::: "memory");   // PDL: upstream done

    const int blk = blockIdx.x;      // b*NSEG + n
    const int tid = threadIdx.x;
    const int c   = tid >> 2;        // 0..255
    const int o   = tid & 3;         // 0..3

    const float val = __int_as_float(g_gmax[blk * C_ + c]);  // >= 0 by construction
    mlp[o][c] = val * g_wf[tid];
    __syncthreads();                 // all reads of this block's slice done

    // restore the zero invariant (each block owns its own 256-int slice)
    if (tid < C_) g_gmax[blk * C_ + tid] = 0;

    const int wid = tid >> 5, lane = tid & 31;
    if (wid < 4) {
        float s = 0.0f;
        #pragma unroll
        for (int k = 0; k < 8; k++) s += mlp[wid][lane + 32 * k];
        #pragma unroll
        for (int d = 16; d >= 1; d >>= 1) s += __shfl_xor_sync(0xffffffffu, s, d);
        if (lane == 0)
            out[blk * 4 + wid] = 1.0f / (1.0f + expf(-(s + g_bias[wid])));
    }
}

// ---------------------------------------------------------------------------
extern "C" void kernel_launch(void* const* d_in, const int* in_sizes, int n_in,
                              void* d_out, int out_size) {
    const float* enc   = (const float*)d_in[0];  // [4,256,256,256] f32
    const float* w1    = (const float*)d_in[1];  // [256,128]
    const float* b1    = (const float*)d_in[2];  // [128]
    const float* w2    = (const float*)d_in[3];  // [128,4]
    const float* b2    = (const float*)d_in[4];  // [4]
    const int*   masks = (const int*)d_in[5];    // [4,1,256,256] i32

    seg_pool_kernel<<<NBLK1 + 1, THREADS1>>>(enc, masks, w1, b1, w2, b2);

    // mlp as a PDL secondary: launch overlaps the pooling wave.
    cudaLaunchConfig_t cfg = {};
    cfg.gridDim  = dim3(B_ * NSEG);
    cfg.blockDim = dim3(1024);
    cudaLaunchAttribute attr[1];
    attr[0].id = cudaLaunchAttributeProgrammaticStreamSerialization;
    attr[0].val.programmaticStreamSerializationAllowed = 1;
    cfg.attrs = attr;
    cfg.numAttrs = 1;
    cudaLaunchKernelEx(&cfg, mlp_kernel, (float*)d_out);
}

// round 17
// speedup vs baseline: 1.0736x; 1.0736x over previous
#include <cuda_runtime.h>
#include <math.h>

// Problem constants (fixed shapes from reference setup_inputs)
#define B_      4
#define C_      256
#define P_      65536          // H*W = 256*256
#define NSEG    32             // object ids 1..32
#define PT      1024           // pixels per tile
#define TILES_PER_B (P_ / PT)  // 64
#define CH      128            // channels per block (tile split in 2)
#define NQH     (CH / 4)       // 32 channel-quads per block
#define NBLK1   (B_ * TILES_PER_B * 2)  // 512 pooling blocks (+1 wf block)
#define THREADS1 256

// Global segmented maxima as non-negative float bit-patterns: [b][seg][c], 128 KB.
// INVARIANT: zero at kernel_launch entry (zero-initialized at module load;
// mlp_kernel re-zeros after consuming, so every call/replay sees zeros).
__device__ int g_gmax[B_ * NSEG * C_];
// Fused MLP weight Wf = w1@w2 [256][4] and bias = b2 + b1@w2 [4]
__device__ float g_wf[C_ * 4];
__device__ float g_bias[4];

// ---------------------------------------------------------------------------
// Phase 1: per-(tile, channel-half) segmented max. accum [cquad][id][4ch];
// one LDS.128 snapshots 4 channels' maxima for a pixel's id. Non-negative
// float bits (init 0 == clamp at 0; int cmp == float cmp); stale snapshots
// safe (monotone). 4+4 double-buffered loads; 512 blocks -> ~3.5 CTAs/SM.
// Flush: fire-and-forget REDG.MAX to g_gmax — NO fence (R14 measured +20us).
// PDL: launch_dependents at entry lets the (tiny) mlp kernel co-schedule;
// its griddepcontrol.wait releases after this grid completes + mem flush.
// The LAST block computes Wf = w1@w2 and bias = b2 + b1@w2 instead.
// ---------------------------------------------------------------------------
__global__ __launch_bounds__(THREADS1, 4)
void seg_pool_kernel(const float* __restrict__ enc, const int* __restrict__ masks,
                     const float* __restrict__ w1, const float* __restrict__ b1,
                     const float* __restrict__ w2, const float* __restrict__ b2) {
    asm volatile("griddepcontrol.launch_dependents;");

    const int blk  = blockIdx.x;
    const int tid  = threadIdx.x;
    const int warp = tid >> 5;
    const int lane = tid & 31;

    if (blk == NBLK1) {
        // ---- fused-weight block: 8 warps cover 256 c-rows, 32 rows each ----
        for (int r = 0; r < 32; r++) {
            const int c = r * 8 + warp;
            float a0 = 0.f, a1 = 0.f, a2 = 0.f, a3 = 0.f;
            #pragma unroll
            for (int k = 0; k < 4; k++) {
                const int j = lane + 32 * k;
                const float a = w1[c * 128 + j];
                const float4 wr = *reinterpret_cast<const float4*>(w2 + j * 4);
                a0 = fmaf(a, wr.x, a0); a1 = fmaf(a, wr.y, a1);
                a2 = fmaf(a, wr.z, a2); a3 = fmaf(a, wr.w, a3);
            }
            #pragma unroll
            for (int d = 16; d >= 1; d >>= 1) {
                a0 += __shfl_xor_sync(0xffffffffu, a0, d);
                a1 += __shfl_xor_sync(0xffffffffu, a1, d);
                a2 += __shfl_xor_sync(0xffffffffu, a2, d);
                a3 += __shfl_xor_sync(0xffffffffu, a3, d);
            }
            if (lane == 0)
                *reinterpret_cast<float4*>(g_wf + c * 4) = make_float4(a0, a1, a2, a3);
        }
        if (warp == 0) {
            float s0 = 0.f, s1 = 0.f, s2 = 0.f, s3 = 0.f;
            #pragma unroll
            for (int k = 0; k < 4; k++) {
                const int j = lane + 32 * k;
                const float bv = b1[j];
                const float4 wr = *reinterpret_cast<const float4*>(w2 + j * 4);
                s0 = fmaf(bv, wr.x, s0); s1 = fmaf(bv, wr.y, s1);
                s2 = fmaf(bv, wr.z, s2); s3 = fmaf(bv, wr.w, s3);
            }
            #pragma unroll
            for (int d = 16; d >= 1; d >>= 1) {
                s0 += __shfl_xor_sync(0xffffffffu, s0, d);
                s1 += __shfl_xor_sync(0xffffffffu, s1, d);
                s2 += __shfl_xor_sync(0xffffffffu, s2, d);
                s3 += __shfl_xor_sync(0xffffffffu, s3, d);
            }
            if (lane == 0) {
                g_bias[0] = s0 + b2[0];
                g_bias[1] = s1 + b2[1];
                g_bias[2] = s2 + b2[2];
                g_bias[3] = s3 + b2[3];
            }
        }
        return;
    }

    __shared__ int4 accum4[NQH * 33];           // 16.9 KB
    int* accum = reinterpret_cast<int*>(accum4);

    // block -> (batch, tile, channel-half)
    const int b    = blk / (TILES_PER_B * 2);
    const int rem  = blk % (TILES_PER_B * 2);
    const int tile = rem >> 1;
    const int half = rem & 1;                   // 0: ch 0..127, 1: 128..255
    const int choff = half * CH;

    #pragma unroll
    for (int i = tid; i < NQH * 33 * 4; i += THREADS1) accum[i] = 0;

    const int pbase = tile * PT;
    const int4 idv = reinterpret_cast<const int4*>(masks + (size_t)b * P_ + pbase)[tid];
    const int id0 = idv.x, id1 = idv.y, id2 = idv.z, id3 = idv.w;

    __syncthreads();

    const float* encb = enc + ((size_t)b * C_ + choff) * P_ + pbase;

    #define LOADV(DST, CBASE)                                                   \
        _Pragma("unroll")                                                       \
        for (int u = 0; u < 4; u++)                                             \
            DST[u] = reinterpret_cast<const float4*>(encb + (size_t)((CBASE) + u) * P_)[tid];

    // one channel-quad (4 consecutive channels), 4 pixels per thread
    #define CHECK_PIXEL(CQ, IDX, SRC, COMP)                                     \
    {                                                                           \
        const int4 cur = accum4[(CQ) * 33 + IDX];                               \
        const int base = ((CQ) * 33 + IDX) * 4; int a;                          \
        a = __float_as_int(SRC[0].COMP); if (a > cur.x) atomicMax(&accum[base+0], a); \
        a = __float_as_int(SRC[1].COMP); if (a > cur.y) atomicMax(&accum[base+1], a); \
        a = __float_as_int(SRC[2].COMP); if (a > cur.z) atomicMax(&accum[base+2], a); \
        a = __float_as_int(SRC[3].COMP); if (a > cur.w) atomicMax(&accum[base+3], a); \
    }

    #define PROCESS(SRC, CBASE)                                                 \
    {                                                                           \
        const int cq = (CBASE) >> 2;                                            \
        CHECK_PIXEL(cq, id0, SRC, x)                                            \
        CHECK_PIXEL(cq, id1, SRC, y)                                            \
        CHECK_PIXEL(cq, id2, SRC, z)                                            \
        CHECK_PIXEL(cq, id3, SRC, w)                                            \
    }

    float4 va[4], vb[4];
    LOADV(va, 0)
    #pragma unroll 1
    for (int c0 = 0; c0 < CH; c0 += 8) {
        LOADV(vb, c0 + 4)
        PROCESS(va, c0)
        if (c0 + 8 < CH) { LOADV(va, c0 + 8) }
        PROCESS(vb, c0 + 4)
    }
    #undef LOADV
    #undef PROCESS
    #undef CHECK_PIXEL

    __syncthreads();

    // flush this half's channels straight to global maxima (drop id 0);
    // fire-and-forget REDG.MAX — no round trip, no fence.
    #pragma unroll
    for (int i = tid; i < NSEG * CH; i += THREADS1) {
        const int s  = i >> 7;       // 0..31
        const int cl = i & 127;      // local channel 0..127
        atomicMax(&g_gmax[(b * NSEG + s) * C_ + choff + cl],
                  accum[((cl >> 2) * 33 + s + 1) * 4 + (cl & 3)]);
    }
}

// ---------------------------------------------------------------------------
// Phase 2 (PDL secondary, LIGHTWEIGHT): 128 blocks x 128 threads — only ~3.5
// parked warps/SM while waiting, so the pooling wave keeps its occupancy.
// Thread owns channels {tid, tid+128} x 4 outputs; warp butterfly + 4x4
// shared combine; re-zeros its slice (replay invariant).
// ---------------------------------------------------------------------------
__global__ __launch_bounds__(128)
void mlp_kernel(float* __restrict__ out) {
    __shared__ float part[4][4];

    asm volatile("griddepcontrol.wait;" ::: "memory");   // upstream done + flushed

    const int blk  = blockIdx.x;     // b*NSEG + n
    const int tid  = threadIdx.x;    // 0..127
    const int warp = tid >> 5;
    const int lane = tid & 31;

    const float v0 = __int_as_float(g_gmax[blk * C_ + tid]);        // >= 0
    const float v1 = __int_as_float(g_gmax[blk * C_ + 128 + tid]);
    const float4 w0 = *reinterpret_cast<const float4*>(g_wf + tid * 4);
    const float4 w1v = *reinterpret_cast<const float4*>(g_wf + (128 + tid) * 4);

    // restore the zero invariant (values already in registers)
    g_gmax[blk * C_ + tid] = 0;
    g_gmax[blk * C_ + 128 + tid] = 0;

    float a0 = fmaf(v0, w0.x, v1 * w1v.x);
    float a1 = fmaf(v0, w0.y, v1 * w1v.y);
    float a2 = fmaf(v0, w0.z, v1 * w1v.z);
    float a3 = fmaf(v0, w0.w, v1 * w1v.w);

    #pragma unroll
    for (int d = 16; d >= 1; d >>= 1) {
        a0 += __shfl_xor_sync(0xffffffffu, a0, d);
        a1 += __shfl_xor_sync(0xffffffffu, a1, d);
        a2 += __shfl_xor_sync(0xffffffffu, a2, d);
        a3 += __shfl_xor_sync(0xffffffffu, a3, d);
    }
    if (lane == 0) {
        part[warp][0] = a0; part[warp][1] = a1;
        part[warp][2] = a2; part[warp][3] = a3;
    }
    __syncthreads();

    if (tid < 4) {
        const float s = part[0][tid] + part[1][tid] + part[2][tid] + part[3][tid]
                      + g_bias[tid];
        out[blk * 4 + tid] = 1.0f / (1.0f + expf(-s));
    }
}

// ---------------------------------------------------------------------------
extern "C" void kernel_launch(void* const* d_in, const int* in_sizes, int n_in,
                              void* d_out, int out_size) {
    const float* enc   = (const float*)d_in[0];  // [4,256,256,256] f32
    const float* w1    = (const float*)d_in[1];  // [256,128]
    const float* b1    = (const float*)d_in[2];  // [128]
    const float* w2    = (const float*)d_in[3];  // [128,4]
    const float* b2    = (const float*)d_in[4];  // [4]
    const int*   masks = (const int*)d_in[5];    // [4,1,256,256] i32

    seg_pool_kernel<<<NBLK1 + 1, THREADS1>>>(enc, masks, w1, b1, w2, b2);

    // mlp as a small PDL secondary: launch latency hides under the pooling wave.
    cudaLaunchConfig_t cfg = {};
    cfg.gridDim  = dim3(B_ * NSEG);
    cfg.blockDim = dim3(128);
    cudaLaunchAttribute attr[1];
    attr[0].id = cudaLaunchAttributeProgrammaticStreamSerialization;
    attr[0].val.programmaticStreamSerializationAllowed = 1;
    cfg.attrs = attr;
    cfg.numAttrs = 1;
    cudaLaunchKernelEx(&cfg, mlp_kernel, (float*)d_out);
}